// round 8
// baseline (speedup 1.0000x reference)
#include <cuda_runtime.h>

#define Bsz   4096
#define Tn    512
#define Fdim  4
#define Hn    50
#define TB    32
#define NT    256     // 8 warps; warp owns 6-7 units, lane = batch

// shared byte offsets (16B aligned)
#define O_Q0HH 0                    // [k][u][4g] quads: 50*50*16 = 40000
#define O_Q1IH 40000
#define O_Q1HH 80000
#define O_Q0IH 120000               // [kf][u][4g]: 3200
#define O_BQ0  123200               // [u][4g]: 800
#define O_BQ1  124000               // 800
#define O_H0   124800               // 2 bufs x 50*128 = 12800
#define O_H1   137600               // 12800
#define SMEM_BYTES 150400
#define HB    6400                  // one h buffer (50 rows x 128B)

using u64 = unsigned long long;

__device__ __forceinline__ u64 pack2(float v) {
    u64 r; unsigned i = __float_as_uint(v);
    asm("mov.b64 %0, {%1, %1};" : "=l"(r) : "r"(i));
    return r;
}
__device__ __forceinline__ void unpack2(u64 v, float& a, float& b) {
    unsigned lo, hi;
    asm("mov.b64 {%0, %1}, %2;" : "=r"(lo), "=r"(hi) : "l"(v));
    a = __uint_as_float(lo); b = __uint_as_float(hi);
}
__device__ __forceinline__ void ffma2(u64& d, u64 a, u64 b) {
    asm("fma.rn.f32x2 %0, %1, %2, %0;" : "+l"(d) : "l"(a), "l"(b));
}
__device__ __forceinline__ void lds_v2b64(u64& a, u64& b, unsigned addr) {
    asm("ld.shared.v2.b64 {%0, %1}, [%2];" : "=l"(a), "=l"(b) : "r"(addr));
}
__device__ __forceinline__ float lds_f32(unsigned addr) {
    float v; asm("ld.shared.b32 %0, [%1];" : "=f"(v) : "r"(addr));
    return v;
}
__device__ __forceinline__ void sts_f32(unsigned addr, float v) {
    asm("st.shared.b32 [%0], %1;" :: "r"(addr), "f"(v));
}

__device__ __forceinline__ float sigf(float x) {
    float e = __expf(-x);
    float r;
    asm("rcp.approx.f32 %0, %1;" : "=f"(r) : "f"(1.0f + e));
    return r;
}
__device__ __forceinline__ float tanhf_acc(float x) {
    return fmaf(2.0f, sigf(2.0f * x), -1.0f);   // exact identity
}

// warp owns units [ubase, ubase+U); lane = batch. Gate-pair f32x2:
// accIF = (gate_i, gate_f), accGO = (gate_g, gate_o) for this lane's batch.
template<int U>
__device__ __forceinline__ void run_loop(unsigned sb, int lane, int ubase,
                                         const float4* __restrict__ xr)
{
    const unsigned a_q0hh = sb + O_Q0HH + (unsigned)ubase * 16;
    const unsigned a_q1ih = sb + O_Q1IH + (unsigned)ubase * 16;
    const unsigned a_q1hh = sb + O_Q1HH + (unsigned)ubase * 16;
    const unsigned a_q0ih = sb + O_Q0IH + (unsigned)ubase * 16;
    const unsigned a_bq0  = sb + O_BQ0  + (unsigned)ubase * 16;
    const unsigned a_bq1  = sb + O_BQ1  + (unsigned)ubase * 16;
    const unsigned a_h0   = sb + O_H0;
    const unsigned a_h1   = sb + O_H1;
    const unsigned lb     = (unsigned)lane * 4;
    const unsigned hst    = a_h0 + (unsigned)ubase * 128 + lb;  // h0 store base
    const unsigned hst1   = a_h1 + (unsigned)ubase * 128 + lb;

    float c0[U], c1[U];
    #pragma unroll
    for (int u = 0; u < U; ++u) { c0[u] = 0.f; c1[u] = 0.f; }

    float4 xv = xr[0];
    float4 xn = xv;

    for (int t = 0; t < Tn; ++t) {
        if (t + 1 < Tn) xn = xr[t + 1];
        const unsigned cur = (t & 1) ? HB : 0u;
        const unsigned nxt = HB - cur;

        u64 aIF[U], aGO[U];

        // ---- layer 0: bias + Wih0*x + Whh0*h0_prev ----
        #pragma unroll
        for (int u = 0; u < U; ++u)
            lds_v2b64(aIF[u], aGO[u], a_bq0 + u * 16);
        {
            u64 xs0 = pack2(xv.x), xs1 = pack2(xv.y), xs2 = pack2(xv.z), xs3 = pack2(xv.w);
            #pragma unroll
            for (int u = 0; u < U; ++u) {
                u64 wIF, wGO;
                lds_v2b64(wIF, wGO, a_q0ih + 0 * 800 + u * 16);
                ffma2(aIF[u], wIF, xs0); ffma2(aGO[u], wGO, xs0);
                lds_v2b64(wIF, wGO, a_q0ih + 1 * 800 + u * 16);
                ffma2(aIF[u], wIF, xs1); ffma2(aGO[u], wGO, xs1);
                lds_v2b64(wIF, wGO, a_q0ih + 2 * 800 + u * 16);
                ffma2(aIF[u], wIF, xs2); ffma2(aGO[u], wGO, xs2);
                lds_v2b64(wIF, wGO, a_q0ih + 3 * 800 + u * 16);
                ffma2(aIF[u], wIF, xs3); ffma2(aGO[u], wGO, xs3);
            }
        }
        #pragma unroll 10
        for (int k = 0; k < Hn; ++k) {
            u64 hd = pack2(lds_f32(a_h0 + cur + k * 128 + lb));
            const unsigned wk = a_q0hh + k * 800;
            #pragma unroll
            for (int u = 0; u < U; ++u) {
                u64 wIF, wGO;
                lds_v2b64(wIF, wGO, wk + u * 16);
                ffma2(aIF[u], wIF, hd);
                ffma2(aGO[u], wGO, hd);
            }
        }
        // ---- layer 0 epilogue: c in regs, scalar h -> h0[nxt] (coalesced) ----
        #pragma unroll
        for (int u = 0; u < U; ++u) {
            float gi, gf, gg, go;
            unpack2(aIF[u], gi, gf);
            unpack2(aGO[u], gg, go);
            float c = fmaf(sigf(gf), c0[u], sigf(gi) * tanhf_acc(gg));
            c0[u] = c;
            sts_f32(hst + nxt + u * 128, sigf(go) * tanhf_acc(c));
        }
        __syncthreads();   // single sync per step (R5-proven hazard structure)

        // ---- layer 1: bias + Wih1*h0_new + Whh1*h1_prev ----
        #pragma unroll
        for (int u = 0; u < U; ++u)
            lds_v2b64(aIF[u], aGO[u], a_bq1 + u * 16);
        #pragma unroll 10
        for (int k = 0; k < Hn; ++k) {
            u64 pd = pack2(lds_f32(a_h0 + nxt + k * 128 + lb));
            u64 qd = pack2(lds_f32(a_h1 + cur + k * 128 + lb));
            const unsigned wk1 = a_q1ih + k * 800;
            const unsigned wk2 = a_q1hh + k * 800;
            #pragma unroll
            for (int u = 0; u < U; ++u) {
                u64 wIF1, wGO1, wIF2, wGO2;
                lds_v2b64(wIF1, wGO1, wk1 + u * 16);
                lds_v2b64(wIF2, wGO2, wk2 + u * 16);
                ffma2(aIF[u], wIF1, pd);
                ffma2(aGO[u], wGO1, pd);
                ffma2(aIF[u], wIF2, qd);
                ffma2(aGO[u], wGO2, qd);
            }
        }
        // ---- layer 1 epilogue -> h1[nxt] ----
        #pragma unroll
        for (int u = 0; u < U; ++u) {
            float gi, gf, gg, go;
            unpack2(aIF[u], gi, gf);
            unpack2(aGO[u], gg, go);
            float c = fmaf(sigf(gf), c1[u], sigf(gi) * tanhf_acc(gg));
            c1[u] = c;
            sts_f32(hst1 + nxt + u * 128, sigf(go) * tanhf_acc(c));
        }
        xv = xn;
    }
}

__global__ void __launch_bounds__(NT, 1) lstm2_kernel(
    const float* __restrict__ x,
    const float* __restrict__ Wih0, const float* __restrict__ Whh0,
    const float* __restrict__ bih0, const float* __restrict__ bhh0,
    const float* __restrict__ Wih1, const float* __restrict__ Whh1,
    const float* __restrict__ bih1, const float* __restrict__ bhh1,
    const float* __restrict__ fcW,  const float* __restrict__ fcb,
    float* __restrict__ out)
{
    extern __shared__ float sm[];
    const int tid = threadIdx.x;

    // ---- stage weights as per-unit gate quads [wi,wf,wg,wo] ----
    for (int i = tid; i < Hn * Hn; i += NT) {          // i = k*50 + u
        int k = i / Hn, u = i - k * Hn;
        float* q0 = sm + (O_Q0HH / 4) + i * 4;
        q0[0] = Whh0[(      u) * Hn + k];
        q0[1] = Whh0[( 50 + u) * Hn + k];
        q0[2] = Whh0[(100 + u) * Hn + k];
        q0[3] = Whh0[(150 + u) * Hn + k];
        float* q1i = sm + (O_Q1IH / 4) + i * 4;
        q1i[0] = Wih1[(      u) * Hn + k];
        q1i[1] = Wih1[( 50 + u) * Hn + k];
        q1i[2] = Wih1[(100 + u) * Hn + k];
        q1i[3] = Wih1[(150 + u) * Hn + k];
        float* q1h = sm + (O_Q1HH / 4) + i * 4;
        q1h[0] = Whh1[(      u) * Hn + k];
        q1h[1] = Whh1[( 50 + u) * Hn + k];
        q1h[2] = Whh1[(100 + u) * Hn + k];
        q1h[3] = Whh1[(150 + u) * Hn + k];
    }
    for (int i = tid; i < Fdim * Hn; i += NT) {        // i = kf*50 + u
        int kf = i / Hn, u = i - kf * Hn;
        float* q = sm + (O_Q0IH / 4) + i * 4;
        q[0] = Wih0[(      u) * Fdim + kf];
        q[1] = Wih0[( 50 + u) * Fdim + kf];
        q[2] = Wih0[(100 + u) * Fdim + kf];
        q[3] = Wih0[(150 + u) * Fdim + kf];
    }
    for (int u = tid; u < Hn; u += NT) {
        float* b0 = sm + (O_BQ0 / 4) + u * 4;
        b0[0] = bih0[u]       + bhh0[u];
        b0[1] = bih0[50 + u]  + bhh0[50 + u];
        b0[2] = bih0[100 + u] + bhh0[100 + u];
        b0[3] = bih0[150 + u] + bhh0[150 + u];
        float* b1 = sm + (O_BQ1 / 4) + u * 4;
        b1[0] = bih1[u]       + bhh1[u];
        b1[1] = bih1[50 + u]  + bhh1[50 + u];
        b1[2] = bih1[100 + u] + bhh1[100 + u];
        b1[3] = bih1[150 + u] + bhh1[150 + u];
    }
    for (int i = tid; i < (4 * HB) / 4; i += NT)        // zero all 4 h buffers
        sm[(O_H0 / 4) + i] = 0.f;
    __syncthreads();

    const int wid  = tid >> 5;
    const int lane = tid & 31;
    // units per warp: warps 0,1 -> 7; warps 2..7 -> 6 (2*7 + 6*6 = 50)
    // SMSP unit balance: {7+6, 7+6, 6+6, 6+6} = {13,13,12,12}
    const int U     = (wid < 2) ? 7 : 6;
    const int ubase = (wid < 2) ? wid * 7 : 14 + (wid - 2) * 6;

    const unsigned sb = (unsigned)__cvta_generic_to_shared(sm);
    const float4* xr = (const float4*)x + (size_t)(blockIdx.x * TB + lane) * Tn;

    if (U == 7) run_loop<7>(sb, lane, ubase, xr);
    else        run_loop<6>(sb, lane, ubase, xr);

    __syncthreads();

    // ---- final FC: out = fcW @ h1_final + fcb (h1 final in buffer 0) ----
    if (tid < TB * Fdim) {
        int b2 = tid >> 2, f = tid & 3;
        float a = fcb[f];
        const float* h1 = sm + (O_H1 / 4);
        #pragma unroll
        for (int j = 0; j < Hn; ++j)
            a = fmaf(fcW[f * Hn + j], h1[j * 32 + b2], a);
        out[((size_t)blockIdx.x * TB + b2) * Fdim + f] = a;
    }
}

extern "C" void kernel_launch(void* const* d_in, const int* in_sizes, int n_in,
                              void* d_out, int out_size) {
    const float* x    = (const float*)d_in[0];
    const float* Wih0 = (const float*)d_in[1];
    const float* Whh0 = (const float*)d_in[2];
    const float* bih0 = (const float*)d_in[3];
    const float* bhh0 = (const float*)d_in[4];
    const float* Wih1 = (const float*)d_in[5];
    const float* Whh1 = (const float*)d_in[6];
    const float* bih1 = (const float*)d_in[7];
    const float* bhh1 = (const float*)d_in[8];
    const float* fcW  = (const float*)d_in[9];
    const float* fcb  = (const float*)d_in[10];
    float* out = (float*)d_out;

    cudaFuncSetAttribute(lstm2_kernel,
                         cudaFuncAttributeMaxDynamicSharedMemorySize, SMEM_BYTES);
    lstm2_kernel<<<Bsz / TB, NT, SMEM_BYTES>>>(
        x, Wih0, Whh0, bih0, bhh0, Wih1, Whh1, bih1, bhh1, fcW, fcb, out);
}

// round 9
// speedup vs baseline: 1.5412x; 1.5412x over previous
#include <cuda_runtime.h>

#define Bsz   4096
#define Tn    512
#define Fdim  4
#define Hn    50
#define TB    32
#define NT    256
#define ACT   200     // active threads: u(50) x bg(4); thread owns 1 unit x 8 batches

// shared byte offsets (16B aligned)
#define O_Q0HH 0                    // [k][u][4g] quads: 50*50*16 = 40000
#define O_Q1IH 40000
#define O_Q1HH 80000
#define O_Q0IH 120000               // [kf][u][4g]: 3200
#define O_BQ0  123200               // [u][4g]: 800
#define O_BQ1  124000               // 800
#define O_H0   124800               // 2 bufs x 50*144 = 14400
#define O_H1   139200               // 14400
#define O_XB   153600               // 2 bufs x [4kf][32b] = 1024
#define SMEM_BYTES 154624
#define HSTR   144                  // bytes per k-row (32 batches*4B + 16 pad)
#define HBUFB  7200                 // one h buffer

using u64 = unsigned long long;

__device__ __forceinline__ u64 pack2(float v) {
    u64 r; unsigned i = __float_as_uint(v);
    asm("mov.b64 %0, {%1, %1};" : "=l"(r) : "r"(i));
    return r;
}
__device__ __forceinline__ u64 pack2two(float a, float b) {
    u64 r;
    asm("mov.b64 %0, {%1, %2};" : "=l"(r) : "r"(__float_as_uint(a)), "r"(__float_as_uint(b)));
    return r;
}
__device__ __forceinline__ void unpack2(u64 v, float& a, float& b) {
    unsigned lo, hi;
    asm("mov.b64 {%0, %1}, %2;" : "=r"(lo), "=r"(hi) : "l"(v));
    a = __uint_as_float(lo); b = __uint_as_float(hi);
}
__device__ __forceinline__ void ffma2(u64& d, u64 a, u64 b) {
    asm("fma.rn.f32x2 %0, %1, %2, %0;" : "+l"(d) : "l"(a), "l"(b));
}
__device__ __forceinline__ float4 lds_f4(unsigned addr) {
    float4 v;
    asm("ld.shared.v4.f32 {%0, %1, %2, %3}, [%4];"
        : "=f"(v.x), "=f"(v.y), "=f"(v.z), "=f"(v.w) : "r"(addr));
    return v;
}
__device__ __forceinline__ void lds_v2b64(u64& a, u64& b, unsigned addr) {
    asm("ld.shared.v2.b64 {%0, %1}, [%2];" : "=l"(a), "=l"(b) : "r"(addr));
}
__device__ __forceinline__ void sts_u64(unsigned addr, u64 v) {
    asm("st.shared.b64 [%0], %1;" :: "r"(addr), "l"(v));
}
__device__ __forceinline__ void sts_f32(unsigned addr, float v) {
    asm("st.shared.b32 [%0], %1;" :: "r"(addr), "f"(v));
}

// MUFU.TANH-based activations (1 MUFU each)
__device__ __forceinline__ float tanha(float x) {
    float r; asm("tanh.approx.f32 %0, %1;" : "=f"(r) : "f"(x));
    return r;
}
__device__ __forceinline__ float sigt(float x) {
    return fmaf(0.5f, tanha(0.5f * x), 0.5f);   // sigmoid via tanh identity
}

__global__ void __launch_bounds__(NT, 1) lstm2_kernel(
    const float* __restrict__ x,
    const float* __restrict__ Wih0, const float* __restrict__ Whh0,
    const float* __restrict__ bih0, const float* __restrict__ bhh0,
    const float* __restrict__ Wih1, const float* __restrict__ Whh1,
    const float* __restrict__ bih1, const float* __restrict__ bhh1,
    const float* __restrict__ fcW,  const float* __restrict__ fcb,
    float* __restrict__ out)
{
    extern __shared__ float sm[];
    const int tid = threadIdx.x;

    // ---- stage weights as per-unit gate quads [wi,wf,wg,wo] ----
    for (int i = tid; i < Hn * Hn; i += NT) {          // i = k*50 + u
        int k = i / Hn, u = i - k * Hn;
        float* q0 = sm + (O_Q0HH / 4) + i * 4;
        q0[0] = Whh0[(      u) * Hn + k];
        q0[1] = Whh0[( 50 + u) * Hn + k];
        q0[2] = Whh0[(100 + u) * Hn + k];
        q0[3] = Whh0[(150 + u) * Hn + k];
        float* q1i = sm + (O_Q1IH / 4) + i * 4;
        q1i[0] = Wih1[(      u) * Hn + k];
        q1i[1] = Wih1[( 50 + u) * Hn + k];
        q1i[2] = Wih1[(100 + u) * Hn + k];
        q1i[3] = Wih1[(150 + u) * Hn + k];
        float* q1h = sm + (O_Q1HH / 4) + i * 4;
        q1h[0] = Whh1[(      u) * Hn + k];
        q1h[1] = Whh1[( 50 + u) * Hn + k];
        q1h[2] = Whh1[(100 + u) * Hn + k];
        q1h[3] = Whh1[(150 + u) * Hn + k];
    }
    for (int i = tid; i < Fdim * Hn; i += NT) {        // i = kf*50 + u
        int kf = i / Hn, u = i - kf * Hn;
        float* q = sm + (O_Q0IH / 4) + i * 4;
        q[0] = Wih0[(      u) * Fdim + kf];
        q[1] = Wih0[( 50 + u) * Fdim + kf];
        q[2] = Wih0[(100 + u) * Fdim + kf];
        q[3] = Wih0[(150 + u) * Fdim + kf];
    }
    for (int u = tid; u < Hn; u += NT) {
        float* b0 = sm + (O_BQ0 / 4) + u * 4;
        b0[0] = bih0[u]       + bhh0[u];
        b0[1] = bih0[50 + u]  + bhh0[50 + u];
        b0[2] = bih0[100 + u] + bhh0[100 + u];
        b0[3] = bih0[150 + u] + bhh0[150 + u];
        float* b1 = sm + (O_BQ1 / 4) + u * 4;
        b1[0] = bih1[u]       + bhh1[u];
        b1[1] = bih1[50 + u]  + bhh1[50 + u];
        b1[2] = bih1[100 + u] + bhh1[100 + u];
        b1[3] = bih1[150 + u] + bhh1[150 + u];
    }
    for (int i = tid; i < (2 * HBUFB * 2 + 1024) / 4; i += NT)   // zero h bufs + x bufs
        sm[(O_H0 / 4) + i] = 0.f;
    __syncthreads();

    const unsigned sb = (unsigned)__cvta_generic_to_shared(sm);
    const unsigned a_q0hh = sb + O_Q0HH;
    const unsigned a_q1ih = sb + O_Q1IH;
    const unsigned a_q1hh = sb + O_Q1HH;
    const unsigned a_q0ih = sb + O_Q0IH;
    const unsigned a_h0   = sb + O_H0;
    const unsigned a_h1   = sb + O_H1;
    const unsigned a_xb   = sb + O_XB;

    // x staging handled by warp 7 (tid 224-255, fully idle otherwise)
    const bool xw = (tid >= 224);
    const int  xl = tid & 31;
    const float4* xr = (const float4*)x + (size_t)(blockIdx.x * TB + xl) * Tn;

    // stage x[0] transposed into xbuf[0]
    if (xw) {
        float4 v = xr[0];
        sts_f32(a_xb + 0 * 128 + xl * 4, v.x);
        sts_f32(a_xb + 1 * 128 + xl * 4, v.y);
        sts_f32(a_xb + 2 * 128 + xl * 4, v.z);
        sts_f32(a_xb + 3 * 128 + xl * 4, v.w);
    }

    const bool act = (tid < ACT);
    const int bg = tid / 50;            // batch group 0..3 (8 batches)
    const int u  = tid - bg * 50;       // unit 0..49
    const unsigned wq_off = (unsigned)u * 16;   // byte offset of this unit's quad in a k-row
    const unsigned hoff   = (unsigned)bg * 32;  // byte offset of this thread's 8 batches

    // bias splats held in registers for the whole loop
    u64 b0s[4], b1s[4];
    if (act) {
        float4 b0 = lds_f4(sb + O_BQ0 + wq_off);
        float4 b1 = lds_f4(sb + O_BQ1 + wq_off);
        b0s[0] = pack2(b0.x); b0s[1] = pack2(b0.y); b0s[2] = pack2(b0.z); b0s[3] = pack2(b0.w);
        b1s[0] = pack2(b1.x); b1s[1] = pack2(b1.y); b1s[2] = pack2(b1.z); b1s[3] = pack2(b1.w);
    }

    float c0[8], c1[8];
    #pragma unroll
    for (int j = 0; j < 8; ++j) { c0[j] = 0.f; c1[j] = 0.f; }

    __syncthreads();    // x[0] + weights visible

    for (int t = 0; t < Tn; ++t) {
        const unsigned cur = (t & 1) ? HBUFB : 0u;
        const unsigned nxt = HBUFB - cur;
        const unsigned xcur = (t & 1) ? 512u : 0u;

        float4 xp;
        if (xw && t + 1 < Tn) xp = xr[t + 1];   // prefetch next x (LDG early)

        u64 acc[4][4];     // [gate i,f,g,o][batch-pair]

        if (act) {
            // ---- layer 0: bias + Wih0*x + Whh0*h0_prev ----
            #pragma unroll
            for (int g = 0; g < 4; ++g)
                #pragma unroll
                for (int bp = 0; bp < 4; ++bp) acc[g][bp] = b0s[g];

            #pragma unroll
            for (int kf = 0; kf < Fdim; ++kf) {
                float4 w = lds_f4(a_q0ih + kf * 800 + wq_off);
                u64 x01, x23, x45, x67;
                lds_v2b64(x01, x23, a_xb + xcur + kf * 128 + hoff);
                lds_v2b64(x45, x67, a_xb + xcur + kf * 128 + hoff + 16);
                u64 w0 = pack2(w.x), w1 = pack2(w.y), w2 = pack2(w.z), w3 = pack2(w.w);
                ffma2(acc[0][0], w0, x01); ffma2(acc[0][1], w0, x23);
                ffma2(acc[0][2], w0, x45); ffma2(acc[0][3], w0, x67);
                ffma2(acc[1][0], w1, x01); ffma2(acc[1][1], w1, x23);
                ffma2(acc[1][2], w1, x45); ffma2(acc[1][3], w1, x67);
                ffma2(acc[2][0], w2, x01); ffma2(acc[2][1], w2, x23);
                ffma2(acc[2][2], w2, x45); ffma2(acc[2][3], w2, x67);
                ffma2(acc[3][0], w3, x01); ffma2(acc[3][1], w3, x23);
                ffma2(acc[3][2], w3, x45); ffma2(acc[3][3], w3, x67);
            }
            #pragma unroll 5
            for (int k = 0; k < Hn; ++k) {
                float4 w = lds_f4(a_q0hh + k * 800 + wq_off);
                u64 h01, h23, h45, h67;
                lds_v2b64(h01, h23, a_h0 + cur + k * HSTR + hoff);
                lds_v2b64(h45, h67, a_h0 + cur + k * HSTR + hoff + 16);
                u64 w0 = pack2(w.x), w1 = pack2(w.y), w2 = pack2(w.z), w3 = pack2(w.w);
                ffma2(acc[0][0], w0, h01); ffma2(acc[0][1], w0, h23);
                ffma2(acc[0][2], w0, h45); ffma2(acc[0][3], w0, h67);
                ffma2(acc[1][0], w1, h01); ffma2(acc[1][1], w1, h23);
                ffma2(acc[1][2], w1, h45); ffma2(acc[1][3], w1, h67);
                ffma2(acc[2][0], w2, h01); ffma2(acc[2][1], w2, h23);
                ffma2(acc[2][2], w2, h45); ffma2(acc[2][3], w2, h67);
                ffma2(acc[3][0], w3, h01); ffma2(acc[3][1], w3, h23);
                ffma2(acc[3][2], w3, h45); ffma2(acc[3][3], w3, h67);
            }
            // ---- layer 0 epilogue: c in regs, h -> h0[nxt] ----
            #pragma unroll
            for (int bp = 0; bp < 4; ++bp) {
                float giA, giB, gfA, gfB, ggA, ggB, goA, goB;
                unpack2(acc[0][bp], giA, giB);
                unpack2(acc[1][bp], gfA, gfB);
                unpack2(acc[2][bp], ggA, ggB);
                unpack2(acc[3][bp], goA, goB);
                float cA = fmaf(sigt(gfA), c0[2 * bp],     sigt(giA) * tanha(ggA));
                float cB = fmaf(sigt(gfB), c0[2 * bp + 1], sigt(giB) * tanha(ggB));
                c0[2 * bp] = cA; c0[2 * bp + 1] = cB;
                float hA = sigt(goA) * tanha(cA);
                float hB = sigt(goB) * tanha(cB);
                sts_u64(a_h0 + nxt + u * HSTR + hoff + bp * 8, pack2two(hA, hB));
            }
        }
        // stage prefetched x[t+1] transposed into xbuf[nxt]
        if (xw && t + 1 < Tn) {
            const unsigned xnxt = 512u - xcur;
            sts_f32(a_xb + xnxt + 0 * 128 + xl * 4, xp.x);
            sts_f32(a_xb + xnxt + 1 * 128 + xl * 4, xp.y);
            sts_f32(a_xb + xnxt + 2 * 128 + xl * 4, xp.z);
            sts_f32(a_xb + xnxt + 3 * 128 + xl * 4, xp.w);
        }
        __syncthreads();   // single sync per step (R5-proven hazard structure)

        if (act) {
            // ---- layer 1: bias + Wih1*h0_new + Whh1*h1_prev ----
            #pragma unroll
            for (int g = 0; g < 4; ++g)
                #pragma unroll
                for (int bp = 0; bp < 4; ++bp) acc[g][bp] = b1s[g];

            #pragma unroll 5
            for (int k = 0; k < Hn; ++k) {
                float4 wa = lds_f4(a_q1ih + k * 800 + wq_off);
                float4 wb = lds_f4(a_q1hh + k * 800 + wq_off);
                u64 p01, p23, p45, p67;    // h0_new pairs
                lds_v2b64(p01, p23, a_h0 + nxt + k * HSTR + hoff);
                lds_v2b64(p45, p67, a_h0 + nxt + k * HSTR + hoff + 16);
                u64 q01, q23, q45, q67;    // h1_prev pairs
                lds_v2b64(q01, q23, a_h1 + cur + k * HSTR + hoff);
                lds_v2b64(q45, q67, a_h1 + cur + k * HSTR + hoff + 16);
                u64 a0 = pack2(wa.x), a1 = pack2(wa.y), a2 = pack2(wa.z), a3 = pack2(wa.w);
                u64 b0 = pack2(wb.x), b1 = pack2(wb.y), b2 = pack2(wb.z), b3 = pack2(wb.w);
                ffma2(acc[0][0], a0, p01); ffma2(acc[0][1], a0, p23);
                ffma2(acc[0][2], a0, p45); ffma2(acc[0][3], a0, p67);
                ffma2(acc[1][0], a1, p01); ffma2(acc[1][1], a1, p23);
                ffma2(acc[1][2], a1, p45); ffma2(acc[1][3], a1, p67);
                ffma2(acc[2][0], a2, p01); ffma2(acc[2][1], a2, p23);
                ffma2(acc[2][2], a2, p45); ffma2(acc[2][3], a2, p67);
                ffma2(acc[3][0], a3, p01); ffma2(acc[3][1], a3, p23);
                ffma2(acc[3][2], a3, p45); ffma2(acc[3][3], a3, p67);
                ffma2(acc[0][0], b0, q01); ffma2(acc[0][1], b0, q23);
                ffma2(acc[0][2], b0, q45); ffma2(acc[0][3], b0, q67);
                ffma2(acc[1][0], b1, q01); ffma2(acc[1][1], b1, q23);
                ffma2(acc[1][2], b1, q45); ffma2(acc[1][3], b1, q67);
                ffma2(acc[2][0], b2, q01); ffma2(acc[2][1], b2, q23);
                ffma2(acc[2][2], b2, q45); ffma2(acc[2][3], b2, q67);
                ffma2(acc[3][0], b3, q01); ffma2(acc[3][1], b3, q23);
                ffma2(acc[3][2], b3, q45); ffma2(acc[3][3], b3, q67);
            }
            // ---- layer 1 epilogue ----
            #pragma unroll
            for (int bp = 0; bp < 4; ++bp) {
                float giA, giB, gfA, gfB, ggA, ggB, goA, goB;
                unpack2(acc[0][bp], giA, giB);
                unpack2(acc[1][bp], gfA, gfB);
                unpack2(acc[2][bp], ggA, ggB);
                unpack2(acc[3][bp], goA, goB);
                float cA = fmaf(sigt(gfA), c1[2 * bp],     sigt(giA) * tanha(ggA));
                float cB = fmaf(sigt(gfB), c1[2 * bp + 1], sigt(giB) * tanha(ggB));
                c1[2 * bp] = cA; c1[2 * bp + 1] = cB;
                float hA = sigt(goA) * tanha(cA);
                float hB = sigt(goB) * tanha(cB);
                sts_u64(a_h1 + nxt + u * HSTR + hoff + bp * 8, pack2two(hA, hB));
            }
        }
        // no sync here: same cross-step hazard proof as R5
    }

    __syncthreads();

    // ---- final FC: out = fcW @ h1_final + fcb (h1 final in buffer 0) ----
    if (tid < TB * Fdim) {
        int b2 = tid >> 2, f = tid & 3;
        float a = fcb[f];
        const float* h1 = sm + (O_H1 / 4);
        #pragma unroll
        for (int j = 0; j < Hn; ++j)
            a = fmaf(fcW[f * Hn + j], h1[j * (HSTR / 4) + b2], a);
        out[((size_t)blockIdx.x * TB + b2) * Fdim + f] = a;
    }
}

extern "C" void kernel_launch(void* const* d_in, const int* in_sizes, int n_in,
                              void* d_out, int out_size) {
    const float* x    = (const float*)d_in[0];
    const float* Wih0 = (const float*)d_in[1];
    const float* Whh0 = (const float*)d_in[2];
    const float* bih0 = (const float*)d_in[3];
    const float* bhh0 = (const float*)d_in[4];
    const float* Wih1 = (const float*)d_in[5];
    const float* Whh1 = (const float*)d_in[6];
    const float* bih1 = (const float*)d_in[7];
    const float* bhh1 = (const float*)d_in[8];
    const float* fcW  = (const float*)d_in[9];
    const float* fcb  = (const float*)d_in[10];
    float* out = (float*)d_out;

    cudaFuncSetAttribute(lstm2_kernel,
                         cudaFuncAttributeMaxDynamicSharedMemorySize, SMEM_BYTES);
    lstm2_kernel<<<Bsz / TB, NT, SMEM_BYTES>>>(
        x, Wih0, Whh0, bih0, bhh0, Wih1, Whh1, bih1, bhh1, fcW, fcb, out);
}

// round 10
// speedup vs baseline: 1.6016x; 1.0391x over previous
#include <cuda_runtime.h>

#define Bsz   4096
#define Tn    512
#define Fdim  4
#define Hn    50
#define TB    32
#define NT    256
#define ACT   200     // active threads: u(50) x bg(4); thread owns 1 unit x 8 batches

// shared byte offsets (16B aligned)
#define O_Q0HH 0                    // [k][u][4g] quads: 50*50*16 = 40000
#define O_Q1IH 40000
#define O_Q1HH 80000
#define O_Q0IH 120000               // [kf][u][4g]: 3200
#define O_BQ0  123200               // [u][4g]: 800
#define O_BQ1  124000               // 800
#define O_H0   124800               // 2 bufs x 50*144 = 14400
#define O_H1   139200               // 14400
#define O_XB   153600               // 2 bufs x [4kf][32b] = 1024
#define SMEM_BYTES 154624
#define HSTR   144                  // bytes per k-row (32 batches*4B + 16 pad)
#define HBUFB  7200                 // one h buffer

using u64 = unsigned long long;

__device__ __forceinline__ u64 pack2(float v) {
    u64 r; unsigned i = __float_as_uint(v);
    asm("mov.b64 %0, {%1, %1};" : "=l"(r) : "r"(i));
    return r;
}
__device__ __forceinline__ u64 pack2two(float a, float b) {
    u64 r;
    asm("mov.b64 %0, {%1, %2};" : "=l"(r) : "r"(__float_as_uint(a)), "r"(__float_as_uint(b)));
    return r;
}
__device__ __forceinline__ void unpack2(u64 v, float& a, float& b) {
    unsigned lo, hi;
    asm("mov.b64 {%0, %1}, %2;" : "=r"(lo), "=r"(hi) : "l"(v));
    a = __uint_as_float(lo); b = __uint_as_float(hi);
}
__device__ __forceinline__ void ffma2(u64& d, u64 a, u64 b) {
    asm("fma.rn.f32x2 %0, %1, %2, %0;" : "+l"(d) : "l"(a), "l"(b));
}
__device__ __forceinline__ float4 lds_f4(unsigned addr) {
    float4 v;
    asm("ld.shared.v4.f32 {%0, %1, %2, %3}, [%4];"
        : "=f"(v.x), "=f"(v.y), "=f"(v.z), "=f"(v.w) : "r"(addr));
    return v;
}
__device__ __forceinline__ void lds_v2b64(u64& a, u64& b, unsigned addr) {
    asm("ld.shared.v2.b64 {%0, %1}, [%2];" : "=l"(a), "=l"(b) : "r"(addr));
}
__device__ __forceinline__ void sts_u64(unsigned addr, u64 v) {
    asm("st.shared.b64 [%0], %1;" :: "r"(addr), "l"(v));
}
__device__ __forceinline__ void sts_f32(unsigned addr, float v) {
    asm("st.shared.b32 [%0], %1;" :: "r"(addr), "f"(v));
}

// MUFU.TANH-based activations (1 MUFU each)
__device__ __forceinline__ float tanha(float x) {
    float r; asm("tanh.approx.f32 %0, %1;" : "=f"(r) : "f"(x));
    return r;
}
__device__ __forceinline__ float sigt(float x) {
    return fmaf(0.5f, tanha(0.5f * x), 0.5f);   // sigmoid via tanh identity
}

#define FMA16(A, W0, W1, W2, W3, V0, V1, V2, V3) do { \
    ffma2(A[0][0], W0, V0); ffma2(A[0][1], W0, V1); \
    ffma2(A[0][2], W0, V2); ffma2(A[0][3], W0, V3); \
    ffma2(A[1][0], W1, V0); ffma2(A[1][1], W1, V1); \
    ffma2(A[1][2], W1, V2); ffma2(A[1][3], W1, V3); \
    ffma2(A[2][0], W2, V0); ffma2(A[2][1], W2, V1); \
    ffma2(A[2][2], W2, V2); ffma2(A[2][3], W2, V3); \
    ffma2(A[3][0], W3, V0); ffma2(A[3][1], W3, V1); \
    ffma2(A[3][2], W3, V2); ffma2(A[3][3], W3, V3); \
} while (0)

// gates -> c (regs), h batch-pairs -> smem at dst
__device__ __forceinline__ void epilogue(u64 acc[4][4], float* c, unsigned dst) {
    #pragma unroll
    for (int bp = 0; bp < 4; ++bp) {
        float giA, giB, gfA, gfB, ggA, ggB, goA, goB;
        unpack2(acc[0][bp], giA, giB);
        unpack2(acc[1][bp], gfA, gfB);
        unpack2(acc[2][bp], ggA, ggB);
        unpack2(acc[3][bp], goA, goB);
        float cA = fmaf(sigt(gfA), c[2 * bp],     sigt(giA) * tanha(ggA));
        float cB = fmaf(sigt(gfB), c[2 * bp + 1], sigt(giB) * tanha(ggB));
        c[2 * bp] = cA; c[2 * bp + 1] = cB;
        sts_u64(dst + bp * 8,
                pack2two(sigt(goA) * tanha(cA), sigt(goB) * tanha(cB)));
    }
}

// layer 0 GEMV: acc = bias + Wih0*x + Whh0*h0_prev
__device__ __forceinline__ void gemv_l0(u64 acc[4][4], const u64* bs,
                                        unsigned a_q0ih, unsigned a_q0hh,
                                        unsigned a_x, unsigned a_h,
                                        unsigned wq_off, unsigned hoff)
{
    #pragma unroll
    for (int g = 0; g < 4; ++g)
        #pragma unroll
        for (int bp = 0; bp < 4; ++bp) acc[g][bp] = bs[g];
    #pragma unroll
    for (int kf = 0; kf < Fdim; ++kf) {
        float4 w = lds_f4(a_q0ih + kf * 800 + wq_off);
        u64 x01, x23, x45, x67;
        lds_v2b64(x01, x23, a_x + kf * 128 + hoff);
        lds_v2b64(x45, x67, a_x + kf * 128 + hoff + 16);
        u64 w0 = pack2(w.x), w1 = pack2(w.y), w2 = pack2(w.z), w3 = pack2(w.w);
        FMA16(acc, w0, w1, w2, w3, x01, x23, x45, x67);
    }
    #pragma unroll 10
    for (int k = 0; k < Hn; ++k) {
        float4 w = lds_f4(a_q0hh + k * 800 + wq_off);
        u64 h01, h23, h45, h67;
        lds_v2b64(h01, h23, a_h + k * HSTR + hoff);
        lds_v2b64(h45, h67, a_h + k * HSTR + hoff + 16);
        u64 w0 = pack2(w.x), w1 = pack2(w.y), w2 = pack2(w.z), w3 = pack2(w.w);
        FMA16(acc, w0, w1, w2, w3, h01, h23, h45, h67);
    }
}

// layer 1 GEMV: acc = bias + Wih1*h0_new + Whh1*h1_prev
__device__ __forceinline__ void gemv_l1(u64 acc[4][4], const u64* bs,
                                        unsigned a_q1ih, unsigned a_q1hh,
                                        unsigned a_h0n, unsigned a_h1p,
                                        unsigned wq_off, unsigned hoff)
{
    #pragma unroll
    for (int g = 0; g < 4; ++g)
        #pragma unroll
        for (int bp = 0; bp < 4; ++bp) acc[g][bp] = bs[g];
    #pragma unroll 5
    for (int k = 0; k < Hn; ++k) {
        float4 wa = lds_f4(a_q1ih + k * 800 + wq_off);
        float4 wb = lds_f4(a_q1hh + k * 800 + wq_off);
        u64 p01, p23, p45, p67;
        lds_v2b64(p01, p23, a_h0n + k * HSTR + hoff);
        lds_v2b64(p45, p67, a_h0n + k * HSTR + hoff + 16);
        u64 q01, q23, q45, q67;
        lds_v2b64(q01, q23, a_h1p + k * HSTR + hoff);
        lds_v2b64(q45, q67, a_h1p + k * HSTR + hoff + 16);
        u64 a0 = pack2(wa.x), a1 = pack2(wa.y), a2 = pack2(wa.z), a3 = pack2(wa.w);
        u64 b0 = pack2(wb.x), b1 = pack2(wb.y), b2 = pack2(wb.z), b3 = pack2(wb.w);
        FMA16(acc, a0, a1, a2, a3, p01, p23, p45, p67);
        FMA16(acc, b0, b1, b2, b3, q01, q23, q45, q67);
    }
}

__global__ void __launch_bounds__(NT, 1) lstm2_kernel(
    const float* __restrict__ x,
    const float* __restrict__ Wih0, const float* __restrict__ Whh0,
    const float* __restrict__ bih0, const float* __restrict__ bhh0,
    const float* __restrict__ Wih1, const float* __restrict__ Whh1,
    const float* __restrict__ bih1, const float* __restrict__ bhh1,
    const float* __restrict__ fcW,  const float* __restrict__ fcb,
    float* __restrict__ out)
{
    extern __shared__ float sm[];
    const int tid = threadIdx.x;

    // ---- stage weights as per-unit gate quads [wi,wf,wg,wo] ----
    for (int i = tid; i < Hn * Hn; i += NT) {          // i = k*50 + u
        int k = i / Hn, u = i - k * Hn;
        float* q0 = sm + (O_Q0HH / 4) + i * 4;
        q0[0] = Whh0[(      u) * Hn + k];
        q0[1] = Whh0[( 50 + u) * Hn + k];
        q0[2] = Whh0[(100 + u) * Hn + k];
        q0[3] = Whh0[(150 + u) * Hn + k];
        float* q1i = sm + (O_Q1IH / 4) + i * 4;
        q1i[0] = Wih1[(      u) * Hn + k];
        q1i[1] = Wih1[( 50 + u) * Hn + k];
        q1i[2] = Wih1[(100 + u) * Hn + k];
        q1i[3] = Wih1[(150 + u) * Hn + k];
        float* q1h = sm + (O_Q1HH / 4) + i * 4;
        q1h[0] = Whh1[(      u) * Hn + k];
        q1h[1] = Whh1[( 50 + u) * Hn + k];
        q1h[2] = Whh1[(100 + u) * Hn + k];
        q1h[3] = Whh1[(150 + u) * Hn + k];
    }
    for (int i = tid; i < Fdim * Hn; i += NT) {        // i = kf*50 + u
        int kf = i / Hn, u = i - kf * Hn;
        float* q = sm + (O_Q0IH / 4) + i * 4;
        q[0] = Wih0[(      u) * Fdim + kf];
        q[1] = Wih0[( 50 + u) * Fdim + kf];
        q[2] = Wih0[(100 + u) * Fdim + kf];
        q[3] = Wih0[(150 + u) * Fdim + kf];
    }
    for (int u = tid; u < Hn; u += NT) {
        float* b0 = sm + (O_BQ0 / 4) + u * 4;
        b0[0] = bih0[u]       + bhh0[u];
        b0[1] = bih0[50 + u]  + bhh0[50 + u];
        b0[2] = bih0[100 + u] + bhh0[100 + u];
        b0[3] = bih0[150 + u] + bhh0[150 + u];
        float* b1 = sm + (O_BQ1 / 4) + u * 4;
        b1[0] = bih1[u]       + bhh1[u];
        b1[1] = bih1[50 + u]  + bhh1[50 + u];
        b1[2] = bih1[100 + u] + bhh1[100 + u];
        b1[3] = bih1[150 + u] + bhh1[150 + u];
    }
    for (int i = tid; i < (2 * HBUFB * 2 + 1024) / 4; i += NT)   // zero h bufs + x bufs
        sm[(O_H0 / 4) + i] = 0.f;
    __syncthreads();

    const unsigned sb = (unsigned)__cvta_generic_to_shared(sm);
    const unsigned a_q0hh = sb + O_Q0HH;
    const unsigned a_q1ih = sb + O_Q1IH;
    const unsigned a_q1hh = sb + O_Q1HH;
    const unsigned a_q0ih = sb + O_Q0IH;
    const unsigned a_h0   = sb + O_H0;
    const unsigned a_h1   = sb + O_H1;
    const unsigned a_xb   = sb + O_XB;

    // x staging handled by warp 7 (tid 224-255, no compute slots)
    const bool xw = (tid >= 224);
    const int  xl = tid & 31;
    const float4* xr = (const float4*)x + (size_t)(blockIdx.x * TB + xl) * Tn;

    // stage x[0] into xbuf[0]
    if (xw) {
        float4 v = xr[0];
        sts_f32(a_xb + 0 * 128 + xl * 4, v.x);
        sts_f32(a_xb + 1 * 128 + xl * 4, v.y);
        sts_f32(a_xb + 2 * 128 + xl * 4, v.z);
        sts_f32(a_xb + 3 * 128 + xl * 4, v.w);
    }

    const bool act = (tid < ACT);
    const bool varA = (tid < 128);      // warps 0-3 variant A; 4-7 variant B
    const int bg = tid / 50;
    const int u  = tid - bg * 50;
    const unsigned wq_off = (unsigned)u * 16;
    const unsigned hoff   = (unsigned)bg * 32;
    const unsigned hrow   = (unsigned)u * HSTR + hoff;

    u64 b0s[4], b1s[4];
    if (act) {
        float4 b0 = lds_f4(sb + O_BQ0 + wq_off);
        float4 b1 = lds_f4(sb + O_BQ1 + wq_off);
        b0s[0] = pack2(b0.x); b0s[1] = pack2(b0.y); b0s[2] = pack2(b0.z); b0s[3] = pack2(b0.w);
        b1s[0] = pack2(b1.x); b1s[1] = pack2(b1.y); b1s[2] = pack2(b1.z); b1s[3] = pack2(b1.w);
    }

    float c0[8], c1[8];
    #pragma unroll
    for (int j = 0; j < 8; ++j) { c0[j] = 0.f; c1[j] = 0.f; }

    __syncthreads();    // x[0] + weights + zeroed h visible

    u64 acc0[4][4], acc1[4][4];

    // ---------- peel t = 0: l0 only ----------
    {
        float4 xp4;
        if (xw) xp4 = xr[1];
        if (act) {
            gemv_l0(acc0, b0s, a_q0ih, a_q0hh, a_xb + 0, a_h0 + 0, wq_off, hoff);
            epilogue(acc0, c0, a_h0 + HBUFB + hrow);
        }
        if (xw) {
            sts_f32(a_xb + 512 + 0 * 128 + xl * 4, xp4.x);
            sts_f32(a_xb + 512 + 1 * 128 + xl * 4, xp4.y);
            sts_f32(a_xb + 512 + 2 * 128 + xl * 4, xp4.z);
            sts_f32(a_xb + 512 + 3 * 128 + xl * 4, xp4.w);
        }
        __syncthreads();
    }

    // ---------- fused intervals: l1(t-1) + l0(t), one sync each ----------
    for (int t = 1; t < Tn; ++t) {
        const unsigned hp = ((t - 1) & 1) ? HBUFB : 0u;   // p = (t-1)&1
        const unsigned hq = HBUFB - hp;                    // 1-p
        const unsigned xc = (t & 1) ? 512u : 0u;

        float4 xp4;
        if (xw && t + 1 < Tn) xp4 = xr[t + 1];

        if (act) {
            if (varA) {
                // A: l1g, l1e, l0g, l0e  (epi early)
                gemv_l1(acc1, b1s, a_q1ih, a_q1hh, a_h0 + hq, a_h1 + hp, wq_off, hoff);
                epilogue(acc1, c1, a_h1 + hq + hrow);
                gemv_l0(acc0, b0s, a_q0ih, a_q0hh, a_xb + xc, a_h0 + hq, wq_off, hoff);
                epilogue(acc0, c0, a_h0 + hp + hrow);
            } else {
                // B: l1g, l0g, l1e, l0e  (epi late) — overlaps A's epi with B's gemv
                gemv_l1(acc1, b1s, a_q1ih, a_q1hh, a_h0 + hq, a_h1 + hp, wq_off, hoff);
                gemv_l0(acc0, b0s, a_q0ih, a_q0hh, a_xb + xc, a_h0 + hq, wq_off, hoff);
                epilogue(acc1, c1, a_h1 + hq + hrow);
                epilogue(acc0, c0, a_h0 + hp + hrow);
            }
        }
        if (xw && t + 1 < Tn) {
            const unsigned xn = 512u - xc;
            sts_f32(a_xb + xn + 0 * 128 + xl * 4, xp4.x);
            sts_f32(a_xb + xn + 1 * 128 + xl * 4, xp4.y);
            sts_f32(a_xb + xn + 2 * 128 + xl * 4, xp4.z);
            sts_f32(a_xb + xn + 3 * 128 + xl * 4, xp4.w);
        }
        __syncthreads();   // single sync per interval (hazards proven above)
    }

    // ---------- final l1(T-1): p = 1 -> reads h1[HBUFB], h0[0]; writes h1[0] ----------
    if (act) {
        gemv_l1(acc1, b1s, a_q1ih, a_q1hh, a_h0 + 0, a_h1 + HBUFB, wq_off, hoff);
        epilogue(acc1, c1, a_h1 + 0 + hrow);
    }
    __syncthreads();

    // ---- final FC: out = fcW @ h1_final + fcb (h1 in buffer 0) ----
    if (tid < TB * Fdim) {
        int b2 = tid >> 2, f = tid & 3;
        float a = fcb[f];
        const float* h1 = sm + (O_H1 / 4);
        #pragma unroll
        for (int j = 0; j < Hn; ++j)
            a = fmaf(fcW[f * Hn + j], h1[j * (HSTR / 4) + b2], a);
        out[((size_t)blockIdx.x * TB + b2) * Fdim + f] = a;
    }
}

extern "C" void kernel_launch(void* const* d_in, const int* in_sizes, int n_in,
                              void* d_out, int out_size) {
    const float* x    = (const float*)d_in[0];
    const float* Wih0 = (const float*)d_in[1];
    const float* Whh0 = (const float*)d_in[2];
    const float* bih0 = (const float*)d_in[3];
    const float* bhh0 = (const float*)d_in[4];
    const float* Wih1 = (const float*)d_in[5];
    const float* Whh1 = (const float*)d_in[6];
    const float* bih1 = (const float*)d_in[7];
    const float* bhh1 = (const float*)d_in[8];
    const float* fcW  = (const float*)d_in[9];
    const float* fcb  = (const float*)d_in[10];
    float* out = (float*)d_out;

    cudaFuncSetAttribute(lstm2_kernel,
                         cudaFuncAttributeMaxDynamicSharedMemorySize, SMEM_BYTES);
    lstm2_kernel<<<Bsz / TB, NT, SMEM_BYTES>>>(
        x, Wih0, Whh0, bih0, bhh0, Wih1, Whh1, bih1, bhh1, fcW, fcb, out);
}